// round 4
// baseline (speedup 1.0000x reference)
#include <cuda_runtime.h>

// Depthwise 3x3 (center tap zero) + residual, NHWC x[32,56,56,256] fp32.
// R3 lesson: batched per-thread MLP is the lever (64.5% DRAM @ 37.6us).
// R4: 2-output-row jam per thread. Input rows r-1..r+2 in a 4x6 register
// window feed output rows r,r+1 -> read amplification 3x -> 2x, batched
// loads 12 -> 16 per step, FMA/load density up. Half-row (28 cols) per
// thread; block (128,2) = one full row-pair; 896 blocks, ~3 clean waves
// at 2 CTAs/SM.

#define Bn 32
#define Hn 56
#define Wn 56
#define C2 128   // 256 channels / 2 per float2
#define SEG 28

__device__ __forceinline__ float2 f2fma(float2 k, float2 v, float2 a) {
    a.x = fmaf(k.x, v.x, a.x);
    a.y = fmaf(k.y, v.y, a.y);
    return a;
}

__global__ __launch_bounds__(256, 2)
void contour_integration_kernel(const float2* __restrict__ x,
                                const float2* __restrict__ k,
                                float2* __restrict__ out)
{
    const int c2 = threadIdx.x;                 // 0..127 channel pair
    const int w0 = threadIdx.y * SEG;           // 0 or 28
    const int idx = blockIdx.x;                 // 0..Bn*Hn/2-1 (row pair)
    const int b  = idx / (Hn / 2);
    const int r  = (idx % (Hn / 2)) * 2;        // first output row of pair

    const float2 Z = make_float2(0.f, 0.f);

    // taps (cross-correlation; center k[1][1] excluded)
    const float2 k00 = __ldg(&k[0 * C2 + c2]);
    const float2 k01 = __ldg(&k[1 * C2 + c2]);
    const float2 k02 = __ldg(&k[2 * C2 + c2]);
    const float2 k10 = __ldg(&k[3 * C2 + c2]);
    const float2 k12 = __ldg(&k[5 * C2 + c2]);
    const float2 k20 = __ldg(&k[6 * C2 + c2]);
    const float2 k21 = __ldg(&k[7 * C2 + c2]);
    const float2 k22 = __ldg(&k[8 * C2 + c2]);

    const bool hm = (r > 0);            // input row r-1 exists
    const bool hp = (r + 2 < Hn);       // input row r+2 exists
    const bool lv = (w0 > 0);           // left halo column exists

    const int rs = Wn * C2;             // row stride in float2
    const int base = ((b * Hn + r) * Wn + w0) * C2 + c2;   // 32-bit safe
    const float2* __restrict__ row1 = x + base;            // input row r
    const float2* __restrict__ row2 = row1 + rs;           // input row r+1
    const float2* __restrict__ row0 = hm ? (row1 - rs) : row1;  // clamped
    const float2* __restrict__ row3 = hp ? (row2 + rs) : row2;  // clamped
    float2* __restrict__ o1 = out + base;
    float2* __restrict__ o2 = o1 + rs;

    // window: win[row 0..3][p 0..5] holds local cols lc = w-1 .. w+4
    float2 win[4][6];

    // prologue: lc=-1 (left halo) + lc=0..4 (always in-bounds: w0+4 <= 32)
    win[0][0] = (lv && hm) ? __ldg(&row0[-C2]) : Z;
    win[1][0] =  lv        ? __ldg(&row1[-C2]) : Z;
    win[2][0] =  lv        ? __ldg(&row2[-C2]) : Z;
    win[3][0] = (lv && hp) ? __ldg(&row3[-C2]) : Z;
    #pragma unroll
    for (int p = 1; p <= 5; ++p) {
        const int lc = p - 1;
        win[0][p] = hm ? __ldg(&row0[lc * C2]) : Z;
        win[1][p] =      __ldg(&row1[lc * C2]);
        win[2][p] =      __ldg(&row2[lc * C2]);
        win[3][p] = hp ? __ldg(&row3[lc * C2]) : Z;
    }

    #pragma unroll
    for (int bidx = 0; bidx < 7; ++bidx) {
        const int w = bidx * 4;

        #pragma unroll
        for (int j = 0; j < 4; ++j) {
            // output row r: input rows r-1,r,r+1 = win rows 0,1,2
            float2 a1 = win[1][j + 1];                  // residual
            a1 = f2fma(k00, win[0][j],     a1);
            a1 = f2fma(k01, win[0][j + 1], a1);
            a1 = f2fma(k02, win[0][j + 2], a1);
            a1 = f2fma(k10, win[1][j],     a1);
            a1 = f2fma(k12, win[1][j + 2], a1);
            a1 = f2fma(k20, win[2][j],     a1);
            a1 = f2fma(k21, win[2][j + 1], a1);
            a1 = f2fma(k22, win[2][j + 2], a1);

            // output row r+1: input rows r,r+1,r+2 = win rows 1,2,3
            float2 a2 = win[2][j + 1];                  // residual
            a2 = f2fma(k00, win[1][j],     a2);
            a2 = f2fma(k01, win[1][j + 1], a2);
            a2 = f2fma(k02, win[1][j + 2], a2);
            a2 = f2fma(k10, win[2][j],     a2);
            a2 = f2fma(k12, win[2][j + 2], a2);
            a2 = f2fma(k20, win[3][j],     a2);
            a2 = f2fma(k21, win[3][j + 1], a2);
            a2 = f2fma(k22, win[3][j + 2], a2);

            o1[(w + j) * C2] = a1;
            o2[(w + j) * C2] = a2;
        }

        // shift window, batch-load next 4 columns (lc = w+5 .. w+8)
        if (bidx < 6) {
            #pragma unroll
            for (int rr = 0; rr < 4; ++rr) {
                win[rr][0] = win[rr][4];
                win[rr][1] = win[rr][5];
            }
            #pragma unroll
            for (int j = 0; j < 4; ++j) {
                const int lc = w + 5 + j;               // compile-time
                const bool cok = (w0 + lc) < Wn;        // warp-uniform
                win[0][2 + j] = (cok && hm) ? __ldg(&row0[lc * C2]) : Z;
                win[1][2 + j] =  cok        ? __ldg(&row1[lc * C2]) : Z;
                win[2][2 + j] =  cok        ? __ldg(&row2[lc * C2]) : Z;
                win[3][2 + j] = (cok && hp) ? __ldg(&row3[lc * C2]) : Z;
            }
        }
    }
}

extern "C" void kernel_launch(void* const* d_in, const int* in_sizes, int n_in,
                              void* d_out, int out_size)
{
    const float2* x = (const float2*)d_in[0];   // [32,56,56,256] fp32
    const float2* k = (const float2*)d_in[1];   // [3,3,256] fp32
    float2* out = (float2*)d_out;

    dim3 block(C2, 2);              // 256 threads: one full row-pair
    dim3 grid(Bn * Hn / 2);         // 896 blocks
    contour_integration_kernel<<<grid, block>>>(x, k, out);
}